// round 17
// baseline (speedup 1.0000x reference)
#include <cuda_runtime.h>
#include <cuda_fp16.h>

#define B    4
#define LQ   512
#define LK   512
#define E    128
#define D    256
#define TL   8            // l-rows per score/context CTA
#define QT   32           // qq per stage tile
#define QBLK 128          // qq per score-CTA
#define NTA  (QBLK / QT)  // 4 tiles per score-CTA
#define NTHR 256
#define QPAD 68           // half2 row stride (272B): rows bank-shifted by 4
#define TILE_F4 (QT * (E / 2) / 4)   // float4 per q tile = 512

#define PSP  520          // ps_h row stride in halves (bank = 4r + c, conflict-free)
#define VSP  264          // vs_h row stride in halves (ldmatrix rows on disjoint bank quads)

// proj mma tiling
#define PROWS 16          // rows per proj CTA -> 256 CTAs
#define KC    64          // K chunk
#define XSP   72          // x_hi/x_lo row stride in halves
#define WSP   136         // w_h row stride in halves (272B)

// convert kernel index space
#define VN4  (B * LQ * D / 4)    // value float4 count (524288)
#define WN4  (D * E / 4)         // one W float4 count (8192)
#define CVT_TOT (VN4 + 2 * WN4)  // 540672 -> 2112 CTAs x 256

// Scratch (allocation-free rule: __device__ globals).
__device__ __half2 g_qproj[B * LQ * (E / 2)];
__device__ __half2 g_kproj[B * LK * (E / 2)];
__device__ float   g_scores[B * LK * LQ];   // exp(score), pre-normalization
__device__ __half  g_vh[B * LQ * D];        // value, fp16 (converted once)
__device__ __half  g_w1h[D * E];            // Wc1 fp16
__device__ __half  g_w2h[D * E];            // Wc2 fp16

__device__ __forceinline__ __half2 tanh_h2(__half2 x) {
    unsigned xu = *reinterpret_cast<unsigned*>(&x);
    unsigned r;
    asm("tanh.approx.f16x2 %0, %1;" : "=r"(r) : "r"(xu));
    return *reinterpret_cast<__half2*>(&r);
}
__device__ __forceinline__ __half2 u2h(unsigned x) {
    __half2 h; *reinterpret_cast<unsigned*>(&h) = x; return h;
}
__device__ __forceinline__ unsigned h2u(__half2 h) {
    return *reinterpret_cast<unsigned*>(&h);
}
__device__ __forceinline__ void cpasync16(void* smem_dst, const void* gsrc) {
    unsigned s = (unsigned)__cvta_generic_to_shared(smem_dst);
    asm volatile("cp.async.cg.shared.global [%0], [%1], 16;" :: "r"(s), "l"(gsrc));
}

// ---------------------------------------------------------------------------
// Pre-convert: value -> g_vh, Wc1 -> g_w1h, Wc2 -> g_w2h (fp16, rn).
// Rounding identical to the previous in-kernel converts (bit-identical output).
// ---------------------------------------------------------------------------
__global__ __launch_bounds__(NTHR) void convert_kernel(
    const float* __restrict__ value,
    const float* __restrict__ Wc1, const float* __restrict__ Wc2)
{
    int i = blockIdx.x * NTHR + threadIdx.x;
    if (i >= CVT_TOT) return;
    const float* src; __half* dst; int off;
    if (i < VN4)            { src = value; dst = g_vh;  off = i; }
    else if (i < VN4 + WN4) { src = Wc1;   dst = g_w1h; off = i - VN4; }
    else                    { src = Wc2;   dst = g_w2h; off = i - VN4 - WN4; }
    float4 v = ((const float4*)src)[off];
    uint2 h;
    h.x = h2u(__floats2half2_rn(v.x, v.y));
    h.y = h2u(__floats2half2_rn(v.z, v.w));
    *(uint2*)&dst[off * 4] = h;
}

// ---------------------------------------------------------------------------
// Tensor-core projection: O[r][e] = sum_d X[r][d] * W[d][e], half2 output.
// Grid (128, 2 sides) = 256 CTAs, 8 warps; warp w owns cols w*16..+15.
// W staged from pre-converted g_w*h via double-buffered cp.async (2/thread/chunk
// replaces 8 LDG + 16 cvt + 8 STS); X chunk register-prefetched.
// Split-X two-pass mma keeps X effectively exact (verified R15/R16).
// ---------------------------------------------------------------------------
__global__ __launch_bounds__(NTHR, 4) void proj_kernel(
    const float* __restrict__ query, const float* __restrict__ key)
{
    const float* X; const __half* Wh; __half2* O;
    if (blockIdx.y == 0) { X = query; Wh = g_w1h; O = g_qproj; }
    else                 { X = key;   Wh = g_w2h; O = g_kproj; }

    const int row0 = blockIdx.x * PROWS;
    const int tid  = threadIdx.x;
    const int w    = tid >> 5;
    const int lane = tid & 31;

    __shared__ __align__(16) __half xhi[PROWS][XSP];    // 2.3 KB
    __shared__ __align__(16) __half xlo[PROWS][XSP];    // 2.3 KB
    __shared__ __align__(16) __half w_h[2][KC][WSP];    // 34.8 KB double buffer

    const int n0 = w * 16;
    const int r  = lane >> 2;
    const int cq = lane & 3;
    const int grp = lane >> 3, rit = lane & 7;
    const int brow_off = (grp & 1) * 8 + rit;
    const int bcol_off = (grp >> 1) * 8;

    // X staging coords (1 float4 per thread per chunk)
    const int xrow = tid >> 4, xkf4 = (tid & 15) * 4;

    // prologue: X chunk 0 into registers, W chunk 0 via cp.async
    float4 xv = *(const float4*)(X + (size_t)(row0 + xrow) * D + xkf4);
    #pragma unroll
    for (int j = 0; j < 4; j++) {
        int i = tid + j * NTHR;                   // 0..1023
        int k = i >> 4, c16 = i & 15;
        cpasync16(&w_h[0][k][c16 * 8], Wh + (size_t)k * E + c16 * 8);
    }
    asm volatile("cp.async.commit_group;");

    float c[2][4];
    #pragma unroll
    for (int t = 0; t < 2; t++)
        #pragma unroll
        for (int i = 0; i < 4; i++) c[t][i] = 0.f;

    #pragma unroll 1
    for (int ch = 0; ch < D / KC; ch++) {
        __syncthreads();                          // prev mma reads done (xhi/xlo, w_h reuse)

        // stage X chunk ch from registers (cvt + STS)
        {
            __half h0 = __float2half_rn(xv.x), h1 = __float2half_rn(xv.y);
            __half h2 = __float2half_rn(xv.z), h3 = __float2half_rn(xv.w);
            uint2 hh;
            hh.x = h2u(__halves2half2(h0, h1));
            hh.y = h2u(__halves2half2(h2, h3));
            *(uint2*)&xhi[xrow][xkf4] = hh;
            uint2 ll;
            ll.x = h2u(__floats2half2_rn(xv.x - __half2float(h0),
                                         xv.y - __half2float(h1)));
            ll.y = h2u(__floats2half2_rn(xv.z - __half2float(h2),
                                         xv.w - __half2float(h3)));
            *(uint2*)&xlo[xrow][xkf4] = ll;
        }
        if (ch + 1 < D / KC) {
            xv = *(const float4*)(X + (size_t)(row0 + xrow) * D + (ch + 1) * KC + xkf4);
            #pragma unroll
            for (int j = 0; j < 4; j++) {
                int i = tid + j * NTHR;
                int k = i >> 4, c16 = i & 15;
                cpasync16(&w_h[(ch + 1) & 1][k][c16 * 8],
                          Wh + (size_t)((ch + 1) * KC + k) * E + c16 * 8);
            }
            asm volatile("cp.async.commit_group;");
            asm volatile("cp.async.wait_group 1;");   // chunk ch's W landed
        } else {
            asm volatile("cp.async.wait_group 0;");
        }
        __syncthreads();                          // X + W visible

        const __half (*wb)[WSP] = w_h[ch & 1];
        unsigned w_base = (unsigned)__cvta_generic_to_shared(&wb[0][0]);

        #pragma unroll
        for (int ks = 0; ks < KC / 16; ks++) {
            const int k16 = ks * 16;
            unsigned ah0 = *(const unsigned*)&xhi[r    ][k16 + 2 * cq];
            unsigned ah1 = *(const unsigned*)&xhi[r + 8][k16 + 2 * cq];
            unsigned ah2 = *(const unsigned*)&xhi[r    ][k16 + 2 * cq + 8];
            unsigned ah3 = *(const unsigned*)&xhi[r + 8][k16 + 2 * cq + 8];
            unsigned al0 = *(const unsigned*)&xlo[r    ][k16 + 2 * cq];
            unsigned al1 = *(const unsigned*)&xlo[r + 8][k16 + 2 * cq];
            unsigned al2 = *(const unsigned*)&xlo[r    ][k16 + 2 * cq + 8];
            unsigned al3 = *(const unsigned*)&xlo[r + 8][k16 + 2 * cq + 8];

            unsigned addr = w_base + ((k16 + brow_off) * WSP + n0 + bcol_off) * 2;
            unsigned b0, b1, b2, b3;
            asm volatile(
                "ldmatrix.sync.aligned.m8n8.x4.trans.shared.b16 {%0,%1,%2,%3}, [%4];"
                : "=r"(b0), "=r"(b1), "=r"(b2), "=r"(b3) : "r"(addr));
            asm volatile(
                "mma.sync.aligned.m16n8k16.row.col.f32.f16.f16.f32 "
                "{%0,%1,%2,%3}, {%4,%5,%6,%7}, {%8,%9}, {%0,%1,%2,%3};"
                : "+f"(c[0][0]), "+f"(c[0][1]), "+f"(c[0][2]), "+f"(c[0][3])
                : "r"(ah0), "r"(ah1), "r"(ah2), "r"(ah3), "r"(b0), "r"(b1));
            asm volatile(
                "mma.sync.aligned.m16n8k16.row.col.f32.f16.f16.f32 "
                "{%0,%1,%2,%3}, {%4,%5,%6,%7}, {%8,%9}, {%0,%1,%2,%3};"
                : "+f"(c[0][0]), "+f"(c[0][1]), "+f"(c[0][2]), "+f"(c[0][3])
                : "r"(al0), "r"(al1), "r"(al2), "r"(al3), "r"(b0), "r"(b1));
            asm volatile(
                "mma.sync.aligned.m16n8k16.row.col.f32.f16.f16.f32 "
                "{%0,%1,%2,%3}, {%4,%5,%6,%7}, {%8,%9}, {%0,%1,%2,%3};"
                : "+f"(c[1][0]), "+f"(c[1][1]), "+f"(c[1][2]), "+f"(c[1][3])
                : "r"(ah0), "r"(ah1), "r"(ah2), "r"(ah3), "r"(b2), "r"(b3));
            asm volatile(
                "mma.sync.aligned.m16n8k16.row.col.f32.f16.f16.f32 "
                "{%0,%1,%2,%3}, {%4,%5,%6,%7}, {%8,%9}, {%0,%1,%2,%3};"
                : "+f"(c[1][0]), "+f"(c[1][1]), "+f"(c[1][2]), "+f"(c[1][3])
                : "r"(al0), "r"(al1), "r"(al2), "r"(al3), "r"(b2), "r"(b3));
        }
    }

    #pragma unroll
    for (int t = 0; t < 2; t++) {
        int n = n0 + t * 8 + 2 * cq;
        O[(size_t)(row0 + r    ) * (E / 2) + n / 2] =
            __floats2half2_rn(c[t][0], c[t][1]);
        O[(size_t)(row0 + r + 8) * (E / 2) + n / 2] =
            __floats2half2_rn(c[t][2], c[t][3]);
    }
}

// ---------------------------------------------------------------------------
// Score kernel (unchanged, at MUFU floor): exp(score) -> g_scores.
// ---------------------------------------------------------------------------
__global__ __launch_bounds__(NTHR, 7) void score_kernel(
    const float* __restrict__ vc, float* __restrict__ sc_out)
{
    const int qblk = blockIdx.x;
    const int l0   = blockIdx.y * TL;
    const int b    = blockIdx.z;
    const int tid  = threadIdx.x;
    const int w    = tid >> 5;
    const int lane = tid & 31;

    __shared__ __align__(16) __half2 ks[TL][QPAD];
    __shared__ __align__(16) __half2 vcs[E / 2];
    __shared__ __align__(16) __half2 qs[2][QT][QPAD];

    for (int i = tid; i < TL * (E / 2); i += NTHR)
        ks[i >> 6][i & 63] = g_kproj[(size_t)(b * LK + l0 + (i >> 6)) * (E / 2) + (i & 63)];
    if (tid < E / 2)
        vcs[tid] = __floats2half2_rn(vc[2 * tid], vc[2 * tid + 1]);

    const float4* qbase = (const float4*)(g_qproj + ((size_t)b * LQ + qblk * QBLK) * (E / 2));

    #pragma unroll
    for (int j = 0; j < 2; j++) {
        int i = tid + j * NTHR;
        cpasync16(&qs[0][i >> 4][(i & 15) * 4], qbase + i);
    }
    asm volatile("cp.async.commit_group;");

    const int lrow = lane >> 2;
    const int qrow = w * 4 + (lane & 3);
    float* orow = sc_out + (size_t)(b * LK + l0 + lrow) * LQ + qblk * QBLK + qrow;

    #pragma unroll 1
    for (int t = 0; t < NTA; t++) {
        __syncthreads();
        if (t + 1 < NTA) {
            const float4* src = qbase + (size_t)(t + 1) * TILE_F4;
            #pragma unroll
            for (int j = 0; j < 2; j++) {
                int i = tid + j * NTHR;
                cpasync16(&qs[(t + 1) & 1][i >> 4][(i & 15) * 4], src + i);
            }
            asm volatile("cp.async.commit_group;");
            asm volatile("cp.async.wait_group 1;");
        } else {
            asm volatile("cp.async.wait_group 0;");
        }
        __syncthreads();

        const uint2* qp = (const uint2*)qs[t & 1][qrow];
        const uint2* kp = (const uint2*)ks[lrow];
        const uint2* vp = (const uint2*)vcs;

        float facc = 0.f;
        #pragma unroll 4
        for (int c = 0; c < E / 16; c++) {
            __half2 acc01 = __float2half2_rn(0.f);
            __half2 acc23 = __float2half2_rn(0.f);
            #pragma unroll
            for (int u = 0; u < 4; u++) {
                const int e4 = c * 4 + u;
                uint2 q = qp[e4];
                uint2 k = kp[e4];
                uint2 v = vp[e4];
                __half2 t01 = tanh_h2(__hadd2(u2h(q.x), u2h(k.x)));
                __half2 t23 = tanh_h2(__hadd2(u2h(q.y), u2h(k.y)));
                acc01 = __hfma2(u2h(v.x), t01, acc01);
                acc23 = __hfma2(u2h(v.y), t23, acc23);
            }
            float2 f01 = __half22float2(acc01);
            float2 f23 = __half22float2(acc23);
            facc += (f01.x + f01.y) + (f23.x + f23.y);
        }
        orow[t * QT] = __expf(facc);
    }
}

// ---------------------------------------------------------------------------
// Fused normalize + tensor-core context.
// Value staged from pre-converted g_vh via double-buffered cp.async:
// L2 traffic halved, staging instrs ~10x fewer, prefetch overlaps mma.
// ---------------------------------------------------------------------------
__global__ __launch_bounds__(NTHR, 4) void context_kernel(
    const float* __restrict__ scores,
    float* __restrict__ att_out, float* __restrict__ ctx_out)
{
    const int l0   = blockIdx.x * TL;
    const int b    = blockIdx.y;
    const int tid  = threadIdx.x;
    const int w    = tid >> 5;
    const int lane = tid & 31;

    __shared__ __align__(16) __half ps_h[16][PSP];      // 16.6 KB (rows 8-15 zero)
    __shared__ __align__(16) __half vs_h[2][32][VSP];   // 33.8 KB double buffer

    for (int i = tid; i < 8 * PSP / 2; i += NTHR)
        ((unsigned*)&ps_h[8][0])[i] = 0u;

    // ---- normalize (warp w owns row l0 + w): no-max softmax ----
    {
        const float4* srow = (const float4*)(scores + (size_t)(b * LK + l0 + w) * LQ);
        float4 v[4];
        float s = 0.f;
        #pragma unroll
        for (int k = 0; k < 4; k++) {
            v[k] = srow[lane + 32 * k];
            s += (v[k].x + v[k].y) + (v[k].z + v[k].w);
        }
        #pragma unroll
        for (int o = 16; o; o >>= 1) s += __shfl_xor_sync(0xffffffffu, s, o);
        const float inv = __fdividef(1.f, s);

        float4* arow = (float4*)(att_out + (size_t)(b * LK + l0 + w) * LQ);
        #pragma unroll
        for (int k = 0; k < 4; k++) {
            v[k].x *= inv; v[k].y *= inv; v[k].z *= inv; v[k].w *= inv;
            arow[lane + 32 * k] = v[k];                       // atten stays f32
            uint2 h;
            h.x = h2u(__floats2half2_rn(v[k].x, v[k].y));
            h.y = h2u(__floats2half2_rn(v[k].z, v[k].w));
            *(uint2*)&ps_h[w][(lane + 32 * k) * 4] = h;       // fp16 for mma
        }
    }

    const __half* vh0 = g_vh + (size_t)b * LQ * D;

    // prologue: stage value chunk 0 (32 rows x 512B = 1024 x 16B, 4/thread)
    #pragma unroll
    for (int j = 0; j < 4; j++) {
        int i = tid + j * NTHR;
        int row = i >> 5, c16 = i & 31;
        cpasync16(&vs_h[0][row][c16 * 8], vh0 + (size_t)row * D + c16 * 8);
    }
    asm volatile("cp.async.commit_group;");

    const int n0  = w * 32;
    const int r   = lane >> 2;
    const int cq  = lane & 3;
    const int grp = lane >> 3, rit = lane & 7;
    const int brow_off = (grp & 1) * 8 + rit;
    const int bcol_off = (grp >> 1) * 8;

    float c[4][4];
    #pragma unroll
    for (int t = 0; t < 4; t++)
        #pragma unroll
        for (int i = 0; i < 4; i++) c[t][i] = 0.f;

    #pragma unroll 1
    for (int ch = 0; ch < LQ / 32; ch++) {
        __syncthreads();                  // prev reads of buf[(ch+1)&1] done; ps_h ready at ch=0
        if (ch + 1 < LQ / 32) {
            const __half* src = vh0 + (size_t)(ch + 1) * 32 * D;
            #pragma unroll
            for (int j = 0; j < 4; j++) {
                int i = tid + j * NTHR;
                int row = i >> 5, c16 = i & 31;
                cpasync16(&vs_h[(ch + 1) & 1][row][c16 * 8], src + (size_t)row * D + c16 * 8);
            }
            asm volatile("cp.async.commit_group;");
            asm volatile("cp.async.wait_group 1;");   // chunk ch landed
        } else {
            asm volatile("cp.async.wait_group 0;");
        }
        __syncthreads();                  // chunk ch visible

        unsigned vs_base = (unsigned)__cvta_generic_to_shared(&vs_h[ch & 1][0][0]);

        #pragma unroll
        for (int ks = 0; ks < 2; ks++) {
            const int kabs = ch * 32 + ks * 16 + 2 * cq;
            const int k0   = ks * 16;
            unsigned a0 = *(const unsigned*)&ps_h[r    ][kabs    ];
            unsigned a1 = *(const unsigned*)&ps_h[r + 8][kabs    ];
            unsigned a2 = *(const unsigned*)&ps_h[r    ][kabs + 8];
            unsigned a3 = *(const unsigned*)&ps_h[r + 8][kabs + 8];

            #pragma unroll
            for (int p = 0; p < 2; p++) {
                unsigned addr = vs_base +
                    ((k0 + brow_off) * VSP + n0 + p * 16 + bcol_off) * 2;
                unsigned b0, b1, b2, b3;
                asm volatile(
                    "ldmatrix.sync.aligned.m8n8.x4.trans.shared.b16 {%0,%1,%2,%3}, [%4];"
                    : "=r"(b0), "=r"(b1), "=r"(b2), "=r"(b3) : "r"(addr));
                float* ca = c[2 * p];
                float* cb = c[2 * p + 1];
                asm volatile(
                    "mma.sync.aligned.m16n8k16.row.col.f32.f16.f16.f32 "
                    "{%0,%1,%2,%3}, {%4,%5,%6,%7}, {%8,%9}, {%0,%1,%2,%3};"
                    : "+f"(ca[0]), "+f"(ca[1]), "+f"(ca[2]), "+f"(ca[3])
                    : "r"(a0), "r"(a1), "r"(a2), "r"(a3), "r"(b0), "r"(b1));
                asm volatile(
                    "mma.sync.aligned.m16n8k16.row.col.f32.f16.f16.f32 "
                    "{%0,%1,%2,%3}, {%4,%5,%6,%7}, {%8,%9}, {%0,%1,%2,%3};"
                    : "+f"(cb[0]), "+f"(cb[1]), "+f"(cb[2]), "+f"(cb[3])
                    : "r"(a0), "r"(a1), "r"(a2), "r"(a3), "r"(b2), "r"(b3));
            }
        }
    }

    float* crow = ctx_out + (size_t)(b * LK + l0 + r) * D;
    #pragma unroll
    for (int t = 0; t < 4; t++) {
        int n = n0 + t * 8 + 2 * cq;
        *(float2*)&crow[n] = make_float2(c[t][0], c[t][1]);
    }
}

// ---------------------------------------------------------------------------
extern "C" void kernel_launch(void* const* d_in, const int* in_sizes, int n_in,
                              void* d_out, int out_size)
{
    const float* query = (const float*)d_in[0];
    const float* key   = (const float*)d_in[1];
    const float* value = (const float*)d_in[2];
    const float* Wc1   = (const float*)d_in[3];
    const float* Wc2   = (const float*)d_in[4];
    const float* vc    = (const float*)d_in[5];

    float* ctx = (float*)d_out;                 // [B, LK, D]
    float* att = ctx + (size_t)B * LK * D;      // [B, LK, LQ]

    float* sc;
    cudaGetSymbolAddress((void**)&sc, g_scores);

    convert_kernel<<<(CVT_TOT + NTHR - 1) / NTHR, NTHR>>>(value, Wc1, Wc2);
    proj_kernel<<<dim3(2048 / PROWS, 2), NTHR>>>(query, key);
    score_kernel<<<dim3(LQ / QBLK, LK / TL, B), NTHR>>>(vc, sc);
    context_kernel<<<dim3(LK / TL, B), NTHR>>>(sc, att, ctx);
}